// round 16
// baseline (speedup 1.0000x reference)
#include <cuda_runtime.h>
#include <cstdint>
#include <math.h>

// ===========================================================================
// LSTM cell, legacy tensor path (sm_100: no tcgen05).
//   Prepass: tf32-round A=concat(h_t,x) and W=[4][K][H] in gmem (no cvt in loop).
//   GEMM: TF32 mma.sync m16n8k8, 3-stage cp.async pipeline (R12 race-free sync).
//   OCCUPANCY build: CTA tile 64 rows x (4 gates x 32 H), warp tile 32x32,
//   acc=32 regs, launch_bounds(256,3) -> 3 CTAs/SM = 24 warps (was 16).
//   Fused LSTM epilogue.
// ===========================================================================

namespace {
constexpr int Bsz = 8192, Hsz = 1024, Ksz = 2048;
constexpr int BM = 64, BK = 16;
constexpr int LDA = 20;              // 16 floats + 4 pad (banks 20g+tg distinct)
constexpr int LDB = 136;             // 128 + 8 (banks 8tg+g distinct)
constexpr int A_STRIDE = BM * LDA;   // 1280 floats
constexpr int B_STRIDE = BK * LDB;   // 2176 floats
constexpr int NSTAGE = 3;
constexpr int SMEM_FLOATS = NSTAGE * (A_STRIDE + B_STRIDE);   // 10368
constexpr int SMEM_BYTES = SMEM_FLOATS * 4;                   // 41472

constexpr size_t A_ELEMS = (size_t)Bsz * Ksz;   // 16M
constexpr size_t W_ELEMS = 4ull * Ksz * Hsz;    // 8M (Ksz*Hsz = 2^21)
}

__device__ float g_A[A_ELEMS];   // tf32-rounded concat(h_t, x), [B][K]
__device__ float g_W[W_ELEMS];   // tf32-rounded weights [gate][K][H]

__device__ __forceinline__ void cp16(float* smem_dst, const float* gsrc) {
    uint32_t s = (uint32_t)__cvta_generic_to_shared(smem_dst);
    asm volatile("cp.async.cg.shared.global [%0], [%1], 16;" :: "r"(s), "l"(gsrc));
}
__device__ __forceinline__ uint32_t f2tf(float f) {
    uint32_t r; asm("cvt.rna.tf32.f32 %0, %1;" : "=r"(r) : "f"(f)); return r;
}
__device__ __forceinline__ void mma_tf32(float* c, const uint32_t* a, const uint32_t* b) {
    asm volatile(
        "mma.sync.aligned.m16n8k8.row.col.f32.tf32.tf32.f32 "
        "{%0,%1,%2,%3}, {%4,%5,%6,%7}, {%8,%9}, {%0,%1,%2,%3};"
        : "+f"(c[0]), "+f"(c[1]), "+f"(c[2]), "+f"(c[3])
        : "r"(a[0]), "r"(a[1]), "r"(a[2]), "r"(a[3]), "r"(b[0]), "r"(b[1]));
}
__device__ __forceinline__ float sigf(float v) { return 1.f / (1.f + __expf(-v)); }

// ---------------------------------------------------------------------------
// Prepass: tf32-round inputs; pack A=[h|x] row-major, W=[4][K][H].
__global__ __launch_bounds__(256)
void lstm_prepass(const float* __restrict__ h_t, const float* __restrict__ x,
                  const float* __restrict__ Wf, const float* __restrict__ Wi,
                  const float* __restrict__ Wc, const float* __restrict__ Wo)
{
    const size_t i4 = (size_t)blockIdx.x * 256 + threadIdx.x;
    const size_t A4 = A_ELEMS / 4, T4 = (A_ELEMS + W_ELEMS) / 4;
    if (i4 >= T4) return;
    float4 v; float4* dst;
    if (i4 < A4) {
        const size_t e = i4 * 4;
        const int m = (int)(e >> 11), k = (int)(e & 2047);
        const float* src = (k < 1024) ? (h_t + (size_t)m * 1024 + k)
                                      : (x + (size_t)m * 1024 + (k - 1024));
        v = *reinterpret_cast<const float4*>(src);
        dst = reinterpret_cast<float4*>(g_A + e);
    } else {
        const size_t w = (i4 - A4) * 4;
        const int g = (int)(w >> 21);
        const size_t r = w & ((1u << 21) - 1);
        const float* W = (g == 0) ? Wf : (g == 1) ? Wi : (g == 2) ? Wc : Wo;
        v = *reinterpret_cast<const float4*>(W + r);
        dst = reinterpret_cast<float4*>(g_W + w);
    }
    v.x = __uint_as_float(f2tf(v.x)); v.y = __uint_as_float(f2tf(v.y));
    v.z = __uint_as_float(f2tf(v.z)); v.w = __uint_as_float(f2tf(v.w));
    *dst = v;
}

// ---------------------------------------------------------------------------
__device__ __forceinline__ void prefetch_tiles(float* smem, int stage, int k0,
                                               int m0, int h0, int tid)
{
    float* As  = smem + stage * A_STRIDE;
    float* Bsm = smem + NSTAGE * A_STRIDE + stage * B_STRIDE;
    {   // A: 64 rows x 16 floats = 256 float4 (1 per thread)
        const int r = tid >> 2, q = tid & 3;
        cp16(&As[r * LDA + q * 4], g_A + (size_t)(m0 + r) * Ksz + k0 + q * 4);
    }
    #pragma unroll
    for (int it = 0; it < 2; ++it) {   // B: 16 rows x 128 cols = 512 float4
        const int lin = tid + it * 256;
        const int r = lin >> 5, q = lin & 31;
        const int col0 = q * 4;
        const int gate = col0 >> 5, hc = col0 & 31;
        cp16(&Bsm[r * LDB + col0],
             g_W + (size_t)gate * (Ksz * Hsz) + (size_t)(k0 + r) * Hsz + h0 + hc);
    }
    asm volatile("cp.async.commit_group;");
}

__global__ __launch_bounds__(256, 3)
void lstm_gemm_fused(const float* __restrict__ c_t,
                     const float* __restrict__ bfp, const float* __restrict__ bip,
                     const float* __restrict__ bcp, const float* __restrict__ bop,
                     float* __restrict__ out, int nchunks)
{
    extern __shared__ float smem[];
    const int tid = threadIdx.x;
    const int m0 = blockIdx.y * BM;
    const int h0 = blockIdx.x * 32;            // 32 H-cols per CTA, all 4 gates

    const int warp = tid >> 5, lane = tid & 31;
    const int wm = warp >> 2, wn = warp & 3;   // 2 x 4 warps, warp tile 32x32
    const int rb = wm * 32;
    const int g = lane >> 2, tg = lane & 3;

    float acc[2][4][4];                        // [m-frag][gate][reg] = 32 regs
    #pragma unroll
    for (int i = 0; i < 2; ++i)
        #pragma unroll
        for (int j = 0; j < 4; ++j)
            #pragma unroll
            for (int t = 0; t < 4; ++t) acc[i][j][t] = 0.f;

    const int KT = Ksz / BK;   // 128
    prefetch_tiles(smem, 0, 0, m0, h0, tid);
    prefetch_tiles(smem, 1, BK, m0, h0, tid);

    int stage = 0;
    for (int kt = 0; kt < KT; ++kt) {
        // RAW: group kt complete in EVERY thread, then publish via barrier.
        if (kt + 1 < KT) asm volatile("cp.async.wait_group 1;");
        else             asm volatile("cp.async.wait_group 0;");
        __syncthreads();
        // WAR-safe: stage (kt+2)%3 last read at iter kt-1, before this barrier.
        if (kt + 2 < KT)
            prefetch_tiles(smem, (stage + 2) % NSTAGE, (kt + 2) * BK, m0, h0, tid);

        const float* As  = smem + stage * A_STRIDE;
        const float* Bsm = smem + NSTAGE * A_STRIDE + stage * B_STRIDE;

        #pragma unroll
        for (int kk = 0; kk < BK; kk += 8) {
            uint32_t aF[2][4];
            #pragma unroll
            for (int i = 0; i < 2; ++i) {
                const int r0 = rb + i * 16 + g;
                aF[i][0] = __float_as_uint(As[r0 * LDA + kk + tg]);
                aF[i][1] = __float_as_uint(As[(r0 + 8) * LDA + kk + tg]);
                aF[i][2] = __float_as_uint(As[r0 * LDA + kk + tg + 4]);
                aF[i][3] = __float_as_uint(As[(r0 + 8) * LDA + kk + tg + 4]);
            }
            uint32_t bF[4][2];
            #pragma unroll
            for (int gate = 0; gate < 4; ++gate) {
                const int c0 = gate * 32 + wn * 8 + g;
                bF[gate][0] = __float_as_uint(Bsm[(kk + tg) * LDB + c0]);
                bF[gate][1] = __float_as_uint(Bsm[(kk + tg + 4) * LDB + c0]);
            }
            #pragma unroll
            for (int i = 0; i < 2; ++i)
                #pragma unroll
                for (int gate = 0; gate < 4; ++gate)
                    mma_tf32(acc[i][gate], aF[i], bF[gate]);
        }
        stage = (stage + 1) % NSTAGE;
    }

    // ---- fused epilogue ----
    const int colg = h0 + wn * 8 + tg * 2;
    const float2 bF2 = *reinterpret_cast<const float2*>(bfp + colg);
    const float2 bI2 = *reinterpret_cast<const float2*>(bip + colg);
    const float2 bC2 = *reinterpret_cast<const float2*>(bcp + colg);
    const float2 bO2 = *reinterpret_cast<const float2*>(bop + colg);
    const size_t BH = (size_t)Bsz * Hsz;

    #pragma unroll
    for (int i = 0; i < 2; ++i) {
        #pragma unroll
        for (int half = 0; half < 2; ++half) {
            const int row = m0 + rb + i * 16 + g + half * 8;
            const int t0 = half * 2;
            const float2 ct2 =
                *reinterpret_cast<const float2*>(c_t + (size_t)row * Hsz + colg);
            float hv[2], cv[2];
            #pragma unroll
            for (int u = 0; u < 2; ++u) {
                const float fpre = acc[i][0][t0 + u] + ((u == 0) ? bF2.x : bF2.y);
                const float ipre = acc[i][1][t0 + u] + ((u == 0) ? bI2.x : bI2.y);
                const float cpre = acc[i][2][t0 + u] + ((u == 0) ? bC2.x : bC2.y);
                const float opre = acc[i][3][t0 + u] + ((u == 0) ? bO2.x : bO2.y);
                const float fv = sigf(fpre);
                const float iv = sigf(ipre);
                const float gv = tanhf(cpre);
                const float ov = sigf(opre);
                const float ctv = (u == 0) ? ct2.x : ct2.y;
                cv[u] = fv * ctv + iv * gv;
                hv[u] = ov * tanhf(cv[u]);
            }
            const size_t off = (size_t)row * Hsz + colg;
            const float2 h2 = make_float2(hv[0], hv[1]);
            const float2 c2 = make_float2(cv[0], cv[1]);
            for (int ch = 0; ch < nchunks - 1; ++ch)
                *reinterpret_cast<float2*>(out + (size_t)ch * BH + off) = h2;
            *reinterpret_cast<float2*>(out + (size_t)(nchunks - 1) * BH + off) =
                (nchunks > 1) ? c2 : h2;
        }
    }
}

// ---------------------------------------------------------------------------
extern "C" void kernel_launch(void* const* d_in, const int* in_sizes, int n_in,
                              void* d_out, int out_size)
{
    const float* x   = (const float*)d_in[0];
    const float* h_t = (const float*)d_in[1];
    const float* c_t = (const float*)d_in[2];
    const float* Wf  = (const float*)d_in[3];
    const float* bf  = (const float*)d_in[4];
    const float* Wi  = (const float*)d_in[5];
    const float* bi  = (const float*)d_in[6];
    const float* Wc  = (const float*)d_in[7];
    const float* bc  = (const float*)d_in[8];
    const float* Wo  = (const float*)d_in[9];
    const float* bo  = (const float*)d_in[10];

    cudaFuncSetAttribute(lstm_gemm_fused, cudaFuncAttributeMaxDynamicSharedMemorySize,
                         SMEM_BYTES);

    const size_t T4 = (A_ELEMS + W_ELEMS) / 4;
    lstm_prepass<<<(unsigned)((T4 + 255) / 256), 256>>>(h_t, x, Wf, Wi, Wc, Wo);

    int nchunks = out_size / (Bsz * Hsz);
    if (nchunks < 1) nchunks = 1;
    dim3 grid(Hsz / 32, Bsz / BM);   // 32 x 128 = 4096 CTAs
    lstm_gemm_fused<<<grid, 256, SMEM_BYTES>>>(c_t, bf, bi, bc, bo,
                                               (float*)d_out, nchunks);
}